// round 13
// baseline (speedup 1.0000x reference)
#include <cuda_runtime.h>
#include <cuda_bf16.h>

// Detection_23785528885376  (B=2, N=8192, C=32)
//
// Math collapse (R0): nn_idx[0]==0 always -> neighbor_feat = relu(f[b,0,:]).
// Per row: gamma = max_c( exp(f_c - f0_c) * f_c ) / max_c f ; out = gamma/||gamma||_2 per batch.
//
// R12 analysis: body is MUFU-pipe bound (512K exps over only 64 SMs ->
// ~640cyc/SMSP serialization). R13: SAME total warps & per-warp work, spread
// over 128 blocks x 256 threads -> per-SM MUFU/LSU/SHFL pressure halves.
// All validated structure kept: single node, zero-atomic packed publish,
// warp-0-only poll (now 2 slots/lane: 64 batch peers), register-resident gamma.

#define DET_N  8192
#define DET_C  32
#define BPB    64              // blocks per batch
#define BLOCK  256             // 8 warps
#define ROWS_PER_BLOCK 128     // DET_N / BPB
#define ROWS_PER_WARP  16
#define MAX_SLOTS 256

__device__ unsigned int       g_seq [MAX_SLOTS];   // last completed seq per block (zero-init)
__device__ unsigned long long g_slot[MAX_SLOTS];   // packed (seq<<32 | float bits)

__global__ void __launch_bounds__(BLOCK)
det_fused_kernel(const float* __restrict__ feat, float* __restrict__ out) {
    const int lane = threadIdx.x & 31;
    const int warp = threadIdx.x >> 5;        // 0..7
    const int seg  = lane >> 3;               // 0..3 : row within float4-load group
    const int sid  = lane & 7;                // 0..7 : 8 lanes per row, 4 channels each
    const int b    = blockIdx.x >> 6;         // BPB == 64
    const int block_row0 = blockIdx.x * ROWS_PER_BLOCK;
    const int warp_row0  = block_row0 + warp * ROWS_PER_WARP;

    __shared__ float sh_red[8];
    __shared__ float sh_inv;
    __shared__ unsigned int sh_tgt;

    const float4* __restrict__ feat4 = (const float4*)feat;

    // issue f0 load first (critical path of u = exp(v-f0)*v)
    float4 f0 = __ldg(&feat4[b * DET_N * (DET_C / 4) + sid]);

    // ---- preload 4x float4 (16 rows / warp, 4 rows per LDG.128) ----
    float4 t[4];
    #pragma unroll
    for (int j = 0; j < 4; j++)
        t[j] = feat4[(warp_row0 + j * 4) * (DET_C / 4) + lane];

    // replay-safe target sequence: previous launch's value + 1 (plain load;
    // prior launch fully ordered before this one; zero on first run)
    if (threadIdx.x == 0) sh_tgt = g_seq[blockIdx.x] + 1u;

    f0.x = fmaxf(f0.x, 0.f); f0.y = fmaxf(f0.y, 0.f);
    f0.z = fmaxf(f0.z, 0.f); f0.w = fmaxf(f0.w, 0.f);

    // ---- per-row: m = max(v), U = max(exp(v-f0)*v)  (independent reductions) ----
    float m[4], u[4];
    #pragma unroll
    for (int j = 0; j < 4; j++) {
        float v0 = fmaxf(t[j].x, 0.f), v1 = fmaxf(t[j].y, 0.f);
        float v2 = fmaxf(t[j].z, 0.f), v3 = fmaxf(t[j].w, 0.f);
        m[j] = fmaxf(fmaxf(v0, v1), fmaxf(v2, v3));
        float u0 = __expf(v0 - f0.x) * v0;
        float u1 = __expf(v1 - f0.y) * v1;
        float u2 = __expf(v2 - f0.z) * v2;
        float u3 = __expf(v3 - f0.w) * v3;
        u[j] = fmaxf(fmaxf(u0, u1), fmaxf(u2, u3));
    }
    // 8 interleaved shfl chains (2 quantities x 4 rows) over the 8-lane segment
    #pragma unroll
    for (int o = 1; o < 8; o <<= 1) {
        #pragma unroll
        for (int j = 0; j < 4; j++) {
            m[j] = fmaxf(m[j], __shfl_xor_sync(0xFFFFFFFFu, m[j], o));
            u[j] = fmaxf(u[j], __shfl_xor_sync(0xFFFFFFFFu, u[j], o));
        }
    }

    float s_arr[4];
    float local = 0.0f;                       // masked sum of gamma^2 (sid==0 lanes)
    #pragma unroll
    for (int j = 0; j < 4; j++) {
        float s = __fdividef(u[j], m[j]);
        s_arr[j] = s;
        if (sid == 0) local += s * s;
    }
    // combine the 4 segment-leader lanes (0,8,16,24): 2 shfls
    local += __shfl_xor_sync(0xFFFFFFFFu, local, 8);
    local += __shfl_xor_sync(0xFFFFFFFFu, local, 16);
    if (lane == 0) sh_red[warp] = local;
    __syncthreads();

    // ---- publish (seq | partial): one plain 64-bit store, no atomics;
    //      then ONLY warp 0 polls the 64 batch-peer slots (2 per lane) ----
    if (warp == 0) {
        const unsigned target = sh_tgt;
        if (lane == 0) {
            float q = sh_red[0];
            #pragma unroll
            for (int w = 1; w < 8; w++) q += sh_red[w];
            unsigned long long pk = ((unsigned long long)target << 32)
                                  | (unsigned long long)__float_as_uint(q);
            *((volatile unsigned long long*)&g_slot[blockIdx.x]) = pk;
            g_seq[blockIdx.x] = target;       // consumed by the NEXT launch only
        }
        volatile unsigned long long* slot0 =
            (volatile unsigned long long*)&g_slot[b * BPB + lane];
        volatile unsigned long long* slot1 =
            (volatile unsigned long long*)&g_slot[b * BPB + 32 + lane];
        unsigned long long v0, v1;
        bool ready;
        do {
            v0 = *slot0;
            v1 = *slot1;
            ready = ((unsigned)(v0 >> 32) >= target) & ((unsigned)(v1 >> 32) >= target);
        } while (!__all_sync(0xFFFFFFFFu, ready));

        float q = __uint_as_float((unsigned)(v0 & 0xFFFFFFFFu))
                + __uint_as_float((unsigned)(v1 & 0xFFFFFFFFu));
        #pragma unroll
        for (int o = 16; o; o >>= 1) q += __shfl_xor_sync(0xFFFFFFFFu, q, o);
        if (lane == 0) sh_inv = rsqrtf(q);
    }
    __syncthreads();
    const float inv = sh_inv;

    // ---- scale from registers; 4 contiguous floats per j ----
    if (sid == 0) {
        #pragma unroll
        for (int j = 0; j < 4; j++)
            out[warp_row0 + j * 4 + seg] = s_arr[j] * inv;
    }
}

extern "C" void kernel_launch(void* const* d_in, const int* in_sizes, int n_in,
                              void* d_out, int out_size) {
    // inputs: [0] coords int32 (unused), [1] features f32 [B,N,C], [2] len_batch
    const float* feat = (const float*)d_in[1];
    const int B = in_sizes[1] / (DET_N * DET_C);
    det_fused_kernel<<<B * BPB, BLOCK>>>(feat, (float*)d_out);
}

// round 14
// speedup vs baseline: 1.2464x; 1.2464x over previous
#include <cuda_runtime.h>
#include <cuda_bf16.h>

// Detection_23785528885376  (B=2, N=8192, C=32)
//
// Math collapse (R0): nn_idx[0]==0 always -> neighbor_feat = relu(f[b,0,:]).
// Per row: gamma = max_c( exp(f_c - f0_c) * f_c ) / max_c f  (div by the row
// scalar commutes with max); out = gamma / ||gamma||_2 per batch.
//
// FINAL CONFIG — validated 4x at 6.6-6.9us (R6/R7/R11/R12). Grid-shape sweep
// complete and two-sided: 32 blocks -> 8.9us (R8), 64 -> 6.6-6.9, 128 -> 8.3us
// (R13). The kernel is latency + barrier-arrival-skew bound; 64 blocks x 512
// threads is the measured optimum. Structural lessons baked in:
//  - single graph node (R1: ~3.7us/node overhead)
//  - zero-atomic barrier: packed (seq|partial) 64-bit plain store per block
//    (R4: serialized ATOMG pair cost ~600cyc)
//  - warp-0-only poll of the 32 batch-peer slots (R5: poll storm congested L2, +3us)
//  - gamma register-resident; f0 load issued first; independent m/u reductions
//    (R7: best kernel-internal time)

#define DET_N  8192
#define DET_C  32
#define BPB    32              // blocks per batch
#define BLOCK  512             // 16 warps
#define ROWS_PER_BLOCK 256
#define ROWS_PER_WARP  16
#define MAX_SLOTS 256

__device__ unsigned int       g_seq [MAX_SLOTS];   // last completed seq per block (zero-init)
__device__ unsigned long long g_slot[MAX_SLOTS];   // packed (seq<<32 | float bits)

__global__ void __launch_bounds__(BLOCK)
det_fused_kernel(const float* __restrict__ feat, float* __restrict__ out) {
    const int lane = threadIdx.x & 31;
    const int warp = threadIdx.x >> 5;        // 0..15
    const int seg  = lane >> 3;               // 0..3 : row within float4-load group
    const int sid  = lane & 7;                // 0..7 : 8 lanes per row, 4 channels each
    const int b    = blockIdx.x >> 5;         // BPB == 32
    const int block_row0 = blockIdx.x * ROWS_PER_BLOCK;
    const int warp_row0  = block_row0 + warp * ROWS_PER_WARP;

    __shared__ float sh_red[16];
    __shared__ float sh_inv;
    __shared__ unsigned int sh_tgt;

    const float4* __restrict__ feat4 = (const float4*)feat;

    // issue f0 load first (critical path of u = exp(v-f0)*v)
    float4 f0 = __ldg(&feat4[b * DET_N * (DET_C / 4) + sid]);

    // ---- preload 4x float4 (16 rows / warp, 4 rows per LDG.128) ----
    float4 t[4];
    #pragma unroll
    for (int j = 0; j < 4; j++)
        t[j] = feat4[(warp_row0 + j * 4) * (DET_C / 4) + lane];

    // replay-safe target sequence: previous launch's value + 1 (plain load;
    // prior launch fully ordered before this one; zero on first run)
    if (threadIdx.x == 0) sh_tgt = g_seq[blockIdx.x] + 1u;

    f0.x = fmaxf(f0.x, 0.f); f0.y = fmaxf(f0.y, 0.f);
    f0.z = fmaxf(f0.z, 0.f); f0.w = fmaxf(f0.w, 0.f);

    // ---- per-row: m = max(v), U = max(exp(v-f0)*v)  (independent reductions) ----
    float m[4], u[4];
    #pragma unroll
    for (int j = 0; j < 4; j++) {
        float v0 = fmaxf(t[j].x, 0.f), v1 = fmaxf(t[j].y, 0.f);
        float v2 = fmaxf(t[j].z, 0.f), v3 = fmaxf(t[j].w, 0.f);
        m[j] = fmaxf(fmaxf(v0, v1), fmaxf(v2, v3));
        float u0 = __expf(v0 - f0.x) * v0;
        float u1 = __expf(v1 - f0.y) * v1;
        float u2 = __expf(v2 - f0.z) * v2;
        float u3 = __expf(v3 - f0.w) * v3;
        u[j] = fmaxf(fmaxf(u0, u1), fmaxf(u2, u3));
    }
    // 8 interleaved shfl chains (2 quantities x 4 rows) over the 8-lane segment
    #pragma unroll
    for (int o = 1; o < 8; o <<= 1) {
        #pragma unroll
        for (int j = 0; j < 4; j++) {
            m[j] = fmaxf(m[j], __shfl_xor_sync(0xFFFFFFFFu, m[j], o));
            u[j] = fmaxf(u[j], __shfl_xor_sync(0xFFFFFFFFu, u[j], o));
        }
    }

    float s_arr[4];
    float local = 0.0f;                       // masked sum of gamma^2 (sid==0 lanes)
    #pragma unroll
    for (int j = 0; j < 4; j++) {
        float s = __fdividef(u[j], m[j]);
        s_arr[j] = s;
        if (sid == 0) local += s * s;
    }
    // combine the 4 segment-leader lanes (0,8,16,24): 2 shfls
    local += __shfl_xor_sync(0xFFFFFFFFu, local, 8);
    local += __shfl_xor_sync(0xFFFFFFFFu, local, 16);
    if (lane == 0) sh_red[warp] = local;
    __syncthreads();

    // ---- publish (seq | partial): one plain 64-bit store, no atomics;
    //      then ONLY warp 0 polls the 32 batch-peer slots ----
    if (warp == 0) {
        const unsigned target = sh_tgt;
        if (lane == 0) {
            float q = sh_red[0];
            #pragma unroll
            for (int w = 1; w < 16; w++) q += sh_red[w];
            unsigned long long pk = ((unsigned long long)target << 32)
                                  | (unsigned long long)__float_as_uint(q);
            *((volatile unsigned long long*)&g_slot[blockIdx.x]) = pk;
            g_seq[blockIdx.x] = target;       // consumed by the NEXT launch only
        }
        volatile unsigned long long* slot =
            (volatile unsigned long long*)&g_slot[b * BPB + lane];
        unsigned long long v;
        bool ready;
        do {
            v = *slot;
            ready = (unsigned)(v >> 32) >= target;
        } while (!__all_sync(0xFFFFFFFFu, ready));

        float q = __uint_as_float((unsigned)(v & 0xFFFFFFFFu));
        #pragma unroll
        for (int o = 16; o; o >>= 1) q += __shfl_xor_sync(0xFFFFFFFFu, q, o);
        if (lane == 0) sh_inv = rsqrtf(q);
    }
    __syncthreads();
    const float inv = sh_inv;

    // ---- scale from registers; 4 contiguous floats per j ----
    if (sid == 0) {
        #pragma unroll
        for (int j = 0; j < 4; j++)
            out[warp_row0 + j * 4 + seg] = s_arr[j] * inv;
    }
}

extern "C" void kernel_launch(void* const* d_in, const int* in_sizes, int n_in,
                              void* d_out, int out_size) {
    // inputs: [0] coords int32 (unused), [1] features f32 [B,N,C], [2] len_batch
    const float* feat = (const float*)d_in[1];
    const int B = in_sizes[1] / (DET_N * DET_C);
    det_fused_kernel<<<B * BPB, BLOCK>>>(feat, (float*)d_out);
}